// round 4
// baseline (speedup 1.0000x reference)
#include <cuda_runtime.h>
#include <stdint.h>

#define BATCH 2
#define Hh 128
#define Ww 128
#define HW (Hh * Ww)          // 16384 nodes
#define NE (2 * HW)           // 32768 edges per batch
#define NL 64                 // labels

// ---------------- static device scratch (no allocation allowed) ------------
__device__ __align__(256) unsigned long long g_keys[BATCH][NE];   // sort keys
__device__ __align__(256) unsigned short     g_cnt[BATCH][HW][NL];// label hist per root
__device__ __align__(256) unsigned short     g_u[BATCH][NE];
__device__ __align__(256) unsigned short     g_v[BATCH][NE];
__device__ __align__(256) float              g_a[BATCH][NE];
__device__ double g_partial[BATCH];

// ---------------- 1. init per-node label histograms (one_hot) --------------
__global__ void k_init_counts(const int* __restrict__ gt) {
    int i = blockIdx.x * blockDim.x + threadIdx.x;   // b*HW + n
    if (i >= BATCH * HW) return;
    int lab = gt[i];
    // 64 ushorts = 128 B per row, zero with 8x16B stores then set one element
    ulonglong2* p = reinterpret_cast<ulonglong2*>(&g_cnt[0][0][0]) + (size_t)i * 8;
    ulonglong2 z; z.x = 0ull; z.y = 0ull;
#pragma unroll
    for (int k = 0; k < 8; k++) p[k] = z;
    reinterpret_cast<unsigned short*>(p)[lab] = 1;
}

// ---------------- 2. build sort keys (descending affinity, idx tiebreak) ---
__global__ void k_build_keys(const float* __restrict__ aff) {
    int i = blockIdx.x * blockDim.x + threadIdx.x;   // b*NE + e
    if (i >= BATCH * NE) return;
    int b = i / NE;
    int e = i - b * NE;
    // affinities are in [0,1): positive floats -> monotone bits | signbit
    unsigned bits = __float_as_uint(aff[i]) | 0x80000000u;
    unsigned key  = ~bits;   // descending affinity under ascending uint sort
    g_keys[b][e] = ((unsigned long long)key << 32) | (unsigned)e;
}

// ---------------- 3. bitonic sort (per batch, in global/L2) ----------------
__global__ void k_sort() {
    unsigned long long* keys = g_keys[blockIdx.x];
    for (int k = 2; k <= NE; k <<= 1) {
        for (int j = k >> 1; j > 0; j >>= 1) {
            for (int i = threadIdx.x; i < NE; i += blockDim.x) {
                int ixj = i ^ j;
                if (ixj > i) {
                    unsigned long long A = keys[i], B = keys[ixj];
                    bool up = ((i & k) == 0);
                    if ((A > B) == up) { keys[i] = B; keys[ixj] = A; }
                }
            }
            __syncthreads();
        }
    }
}

// ---------------- 4. decode sorted edges into streaming arrays -------------
__global__ void k_decode(const float* __restrict__ aff) {
    int i = blockIdx.x * blockDim.x + threadIdx.x;   // b*NE + rank
    if (i >= BATCH * NE) return;
    int b = i / NE;
    int r = i - b * NE;
    unsigned long long kk = g_keys[b][r];
    int e = (int)(kk & 0xffffffffu);
    int c = (e >= HW) ? 1 : 0;
    int p = e - c * HW;
    int row = p >> 7, col = p & (Ww - 1);
    int u = 0, v = 0;                    // invalid boundary edge -> self edge (skip)
    if (!c) { if (row < Hh - 1) { u = p; v = p + Ww; } }
    else    { if (col < Ww - 1) { u = p; v = p + 1;  } }
    g_u[b][r] = (unsigned short)u;
    g_v[b][r] = (unsigned short)v;
    g_a[b][r] = aff[b * NE + e];
}

// ---------------- 5. serial Kruskal + MALIS pair counting (1 warp/batch) ---
__global__ void k_scan(const int* __restrict__ gt) {
    extern __shared__ unsigned short sh[];
    unsigned short* par = sh;             // union-find parent
    unsigned short* szs = sh + HW;        // component size
    unsigned short* nzs = sh + 2 * HW;    // nonzero-label voxel count
    int b = blockIdx.x;

    for (int i = threadIdx.x; i < HW; i += blockDim.x) {
        par[i] = (unsigned short)i;
        szs[i] = 1;
        nzs[i] = (gt[b * HW + i] != 0) ? 1 : 0;
    }
    __syncthreads();
    if (threadIdx.x >= 32) return;        // warp 0 runs the serial scan

    const int lane = threadIdx.x;
    const unsigned short* up_ = g_u[b];
    const unsigned short* vp_ = g_v[b];
    const float*          ap_ = g_a[b];
    unsigned short* cnt_base = &g_cnt[b][0][0];

    double gacc = 0.0;   // uniform across lanes

    for (int e = 0; e < NE; e++) {
        __syncwarp();
        int uu = up_[e];
        int vv = vp_[e];
        if (uu == vv) continue;          // invalid boundary edge (uniform)

        // finds with full path compression; all lanes walk identical chains
        // (LDS broadcast), all write identical compressed values (benign).
        int ru = uu; while (par[ru] != ru) ru = par[ru];
        { int x = uu; while (par[x] != ru) { int nx = par[x]; par[x] = (unsigned short)ru; x = nx; } }
        int rv = vv; while (par[rv] != rv) rv = par[rv];
        { int x = vv; while (par[x] != rv) { int nx = par[x]; par[x] = (unsigned short)rv; x = nx; } }
        if (ru == rv) continue;          // no merge (uniform)

        float a = ap_[e];
        int su = szs[ru], sv = szs[rv];
        int big   = (su >= sv) ? ru : rv;
        int small = ru + rv - big;

        // lane l owns labels {2l, 2l+1}
        ushort2 cu = *reinterpret_cast<const ushort2*>(cnt_base + (size_t)ru * NL + 2 * lane);
        ushort2 cv = *reinterpret_cast<const ushort2*>(cnt_base + (size_t)rv * NL + 2 * lane);
        int prod = (int)cu.y * (int)cv.y + ((lane == 0) ? 0 : (int)cu.x * (int)cv.x); // skip label 0
        int same = __reduce_add_sync(0xffffffffu, prod);

        int tu = nzs[ru], tv = nzs[rv];
        long long npos = same;
        long long nneg = (long long)tu * (long long)tv - (long long)same;
        gacc += (double)npos * ((double)a - 1.0) + (double)nneg * (double)a;

        // merge histograms into big (data already in registers)
        ushort2 cs; cs.x = (unsigned short)(cu.x + cv.x); cs.y = (unsigned short)(cu.y + cv.y);
        *reinterpret_cast<ushort2*>(cnt_base + (size_t)big * NL + 2 * lane) = cs;

        // uniform bookkeeping (all lanes write identical values)
        par[small] = (unsigned short)big;
        szs[big]   = (unsigned short)(su + sv);
        nzs[big]   = (unsigned short)(tu + tv);
    }

    if (lane == 0) g_partial[b] = gacc;
}

// ---------------- 6. finalize scalar ---------------------------------------
__global__ void k_final(float* __restrict__ out) {
    out[0] = (float)(-0.5 * (g_partial[0] + g_partial[1]));
}

// ---------------------------------------------------------------------------
extern "C" void kernel_launch(void* const* d_in, const int* in_sizes, int n_in,
                              void* d_out, int out_size) {
    const float* aff = (const float*)d_in[0];      // [2,2,128,128] f32
    const int*   gt  = (const int*)d_in[1];        // [2,128,128] int32 (JAX x64 off)
    float* out = (float*)d_out;

    cudaFuncSetAttribute(k_scan, cudaFuncAttributeMaxDynamicSharedMemorySize,
                         3 * HW * (int)sizeof(unsigned short));

    k_init_counts<<<(BATCH * HW + 255) / 256, 256>>>(gt);
    k_build_keys <<<(BATCH * NE + 255) / 256, 256>>>(aff);
    k_sort       <<<BATCH, 1024>>>();
    k_decode     <<<(BATCH * NE + 255) / 256, 256>>>(aff);
    k_scan       <<<BATCH, 1024, 3 * HW * (int)sizeof(unsigned short)>>>(gt);
    k_final      <<<1, 1>>>(out);
}

// round 6
// speedup vs baseline: 1.4777x; 1.4777x over previous
#include <cuda_runtime.h>
#include <stdint.h>

#define BATCH 2
#define Hh 128
#define Ww 128
#define HW (Hh * Ww)          // 16384 nodes
#define NE (2 * HW)           // 32768 edges per batch
#define NL 64                 // labels

// ---------------- static device scratch (no allocation allowed) ------------
__device__ __align__(256) unsigned long long g_keys[BATCH][NE];    // sort keys
__device__ __align__(256) unsigned short     g_cnt[BATCH][HW][NL]; // label hist per root
__device__ __align__(256) unsigned short     g_u[BATCH][NE];
__device__ __align__(256) unsigned short     g_v[BATCH][NE];
__device__ __align__(256) float              g_a[BATCH][NE];
__device__ __align__(256) unsigned           g_rec[BATCH][HW];     // merge records
__device__ double g_partial[BATCH];

// ---------------- 1. init per-node label histograms (one_hot) --------------
__global__ void k_init_counts(const int* __restrict__ gt) {
    int i = blockIdx.x * blockDim.x + threadIdx.x;   // b*HW + n
    if (i >= BATCH * HW) return;
    int lab = gt[i];
    ulonglong2* p = reinterpret_cast<ulonglong2*>(&g_cnt[0][0][0]) + (size_t)i * 8;
    ulonglong2 z; z.x = 0ull; z.y = 0ull;
#pragma unroll
    for (int k = 0; k < 8; k++) p[k] = z;
    reinterpret_cast<unsigned short*>(p)[lab] = 1;
}

// ---------------- 2. build sort keys (descending affinity) -----------------
__global__ void k_build_keys(const float* __restrict__ aff) {
    int i = blockIdx.x * blockDim.x + threadIdx.x;   // b*NE + e
    if (i >= BATCH * NE) return;
    int b = i / NE;
    int e = i - b * NE;
    unsigned bits = __float_as_uint(aff[i]) | 0x80000000u;
    unsigned key  = ~bits;   // descending affinity under ascending uint sort
    g_keys[b][e] = ((unsigned long long)key << 32) | (unsigned)e;
}

// ---------------- 3. bitonic sort (per batch, in global/L2) ----------------
__global__ void k_sort() {
    unsigned long long* keys = g_keys[blockIdx.x];
    for (int k = 2; k <= NE; k <<= 1) {
        for (int j = k >> 1; j > 0; j >>= 1) {
            for (int i = threadIdx.x; i < NE; i += blockDim.x) {
                int ixj = i ^ j;
                if (ixj > i) {
                    unsigned long long A = keys[i], B = keys[ixj];
                    bool up = ((i & k) == 0);
                    if ((A > B) == up) { keys[i] = B; keys[ixj] = A; }
                }
            }
            __syncthreads();
        }
    }
}

// ---------------- 4. decode sorted edges into streaming arrays -------------
__global__ void k_decode(const float* __restrict__ aff) {
    int i = blockIdx.x * blockDim.x + threadIdx.x;   // b*NE + rank
    if (i >= BATCH * NE) return;
    int b = i / NE;
    int r = i - b * NE;
    unsigned long long kk = g_keys[b][r];
    int e = (int)(kk & 0xffffffffu);
    int c = (e >= HW) ? 1 : 0;
    int p = e - c * HW;
    int row = p >> 7, col = p & (Ww - 1);
    int u = 0, v = 0;                    // invalid boundary edge -> self edge (skip)
    if (!c) { if (row < Hh - 1) { u = p; v = p + Ww; } }
    else    { if (col < Ww - 1) { u = p; v = p + 1;  } }
    g_u[b][r] = (unsigned short)u;
    g_v[b][r] = (unsigned short)v;
    g_a[b][r] = aff[b * NE + e];
}

// ---------------- 5. two-pass Kruskal + MALIS counting (1 warp/batch) ------
__global__ void k_scan(const int* __restrict__ gt) {
    extern __shared__ unsigned short sh[];
    unsigned short* par = sh;             // union-find parent
    unsigned short* szs = sh + HW;        // component size
    unsigned short* nzs = sh + 2 * HW;    // nonzero-label voxel count
    unsigned* sh_spec = (unsigned*)(sh + 3 * HW);  // 32 speculative root pairs
    float*    sh_af   = (float*)(sh_spec + 32);    // 32 affinities
    int b = blockIdx.x;

    for (int i = threadIdx.x; i < HW; i += blockDim.x) {
        par[i] = (unsigned short)i;
        szs[i] = 1;
        nzs[i] = (gt[b * HW + i] != 0) ? 1 : 0;
    }
    __syncthreads();
    if (threadIdx.x >= 32) return;        // warp 0 only from here on

    const int lane = threadIdx.x;
    const unsigned short* up_ = g_u[b];
    const unsigned short* vp_ = g_v[b];
    const float*          ap_ = g_a[b];

    // ======== PASS 1: union-find, Sum(tutv*a), emit merge records ========
    double gaccA = 0.0;   // uniform across lanes
    int M = 0;            // uniform merge count

    for (int e0 = 0; e0 < NE; e0 += 32) {
        // -- phase A: lane-parallel speculative finds with path compression --
        {
            int e = e0 + lane;
            int uu = up_[e], vv = vp_[e];
            int ru = uu, rv = vv;
            if (uu != vv) {
                while (true) { int p = par[ru]; if (p == ru) break; ru = p; }
                { int x = uu; while (par[x] != ru) { int nx = par[x]; par[x] = (unsigned short)ru; x = nx; } }
                while (true) { int p = par[rv]; if (p == rv) break; rv = p; }
                { int x = vv; while (par[x] != rv) { int nx = par[x]; par[x] = (unsigned short)rv; x = nx; } }
            }
            sh_spec[lane] = (unsigned)ru | ((unsigned)rv << 16);
            sh_af[lane]   = ap_[e];
        }
        __syncwarp();
        // -- phase B: serial resolution (uniform across lanes, no divergence) --
#pragma unroll 1
        for (int i = 0; i < 32; i++) {
            unsigned sp = sh_spec[i];
            int a1 = (int)(sp & 0xffffu);
            int b1 = (int)(sp >> 16);
            if (a1 == b1) continue;
            while (true) { int p = par[a1]; if (p == a1) break; a1 = p; }
            while (true) { int p = par[b1]; if (p == b1) break; b1 = p; }
            if (a1 == b1) continue;
            int su = szs[a1], sv = szs[b1];
            unsigned bigRv = (su < sv) ? 1u : 0u;
            int big   = bigRv ? b1 : a1;
            int small = a1 + b1 - big;
            par[small] = (unsigned short)big;
            int tu = nzs[a1], tv = nzs[b1];
            szs[big] = (unsigned short)(su + sv);
            nzs[big] = (unsigned short)(tu + tv);
            gaccA += (double)(tu * tv) * (double)sh_af[i];
            if (lane == 0)
                g_rec[b][M] = (unsigned)a1 | ((unsigned)b1 << 16) | (bigRv << 31);
            M++;
        }
        __syncwarp();
    }

    __threadfence_block();
    __syncwarp();

    // ======== PASS 2: histogram replay, Sum(same) (lane-private, MLP) ========
    long long acc = 0;
    unsigned short* cnt = &g_cnt[b][0][0];
    const unsigned* rec = g_rec[b];
    const int off = 2 * lane;

#pragma unroll 4
    for (int m = 0; m < M; m++) {
        unsigned r = rec[m];
        int ru = (int)(r & 0xffffu);
        int rv = (int)((r >> 16) & 0x7fffu);
        int big = (r >> 31) ? rv : ru;
        ushort2 cu = *reinterpret_cast<const ushort2*>(cnt + ru * NL + off);
        ushort2 cv = *reinterpret_cast<const ushort2*>(cnt + rv * NL + off);
        int prod = (int)cu.y * (int)cv.y + (lane ? (int)cu.x * (int)cv.x : 0); // skip label 0
        acc += prod;
        ushort2 cs;
        cs.x = (unsigned short)(cu.x + cv.x);
        cs.y = (unsigned short)(cu.y + cv.y);
        *reinterpret_cast<ushort2*>(cnt + big * NL + off) = cs;
    }

    // reduce Sum(same) across lanes
#pragma unroll
    for (int s = 16; s; s >>= 1)
        acc += __shfl_xor_sync(0xffffffffu, acc, s);

    if (lane == 0)
        g_partial[b] = gaccA - (double)acc;   // Sum over merges of (tutv*a - same)
}

// ---------------- 6. finalize scalar ---------------------------------------
__global__ void k_final(float* __restrict__ out) {
    out[0] = (float)(-0.5 * (g_partial[0] + g_partial[1]));
}

// ---------------------------------------------------------------------------
extern "C" void kernel_launch(void* const* d_in, const int* in_sizes, int n_in,
                              void* d_out, int out_size) {
    const float* aff = (const float*)d_in[0];      // [2,2,128,128] f32
    const int*   gt  = (const int*)d_in[1];        // [2,128,128] int32
    float* out = (float*)d_out;

    int shbytes = 3 * HW * (int)sizeof(unsigned short) + 32 * 4 + 32 * 4;
    cudaFuncSetAttribute(k_scan, cudaFuncAttributeMaxDynamicSharedMemorySize, shbytes);

    k_init_counts<<<(BATCH * HW + 255) / 256, 256>>>(gt);
    k_build_keys <<<(BATCH * NE + 255) / 256, 256>>>(aff);
    k_sort       <<<BATCH, 1024>>>();
    k_decode     <<<(BATCH * NE + 255) / 256, 256>>>(aff);
    k_scan       <<<BATCH, 256, shbytes>>>(gt);
    k_final      <<<1, 1>>>(out);
}

// round 8
// speedup vs baseline: 2.2480x; 1.5213x over previous
#include <cuda_runtime.h>
#include <stdint.h>

#define BATCH 2
#define Hh 128
#define Ww 128
#define HW (Hh * Ww)          // 16384 nodes
#define NE (2 * HW)           // 32768 edges per batch
#define NL 64                 // labels
#define FULLW 0xffffffffu

// ---------------- static device scratch (no allocation allowed) ------------
__device__ __align__(256) unsigned long long g_keys[BATCH][NE];    // sort keys
__device__ __align__(256) unsigned short     g_cnt[BATCH][HW][NL]; // label hist per root
__device__ __align__(256) unsigned short     g_u[BATCH][NE];
__device__ __align__(256) unsigned short     g_v[BATCH][NE];
__device__ __align__(256) float              g_a[BATCH][NE];
__device__ __align__(256) unsigned           g_rec[BATCH][HW];     // merge records
__device__ double g_partial[BATCH];

// ---------------- 1. init per-node label histograms (one_hot) --------------
__global__ void k_init_counts(const int* __restrict__ gt) {
    int i = blockIdx.x * blockDim.x + threadIdx.x;   // b*HW + n
    if (i >= BATCH * HW) return;
    int lab = gt[i];
    ulonglong2* p = reinterpret_cast<ulonglong2*>(&g_cnt[0][0][0]) + (size_t)i * 8;
    ulonglong2 z; z.x = 0ull; z.y = 0ull;
#pragma unroll
    for (int k = 0; k < 8; k++) p[k] = z;
    reinterpret_cast<unsigned short*>(p)[lab] = 1;
}

// ---------------- 2. build sort keys (descending affinity) -----------------
__global__ void k_build_keys(const float* __restrict__ aff) {
    int i = blockIdx.x * blockDim.x + threadIdx.x;   // b*NE + e
    if (i >= BATCH * NE) return;
    int b = i / NE;
    int e = i - b * NE;
    unsigned bits = __float_as_uint(aff[i]) | 0x80000000u;
    unsigned key  = ~bits;   // descending affinity under ascending uint sort
    g_keys[b][e] = ((unsigned long long)key << 32) | (unsigned)e;
}

// ---------------- 3. bitonic sort, shared-memory tiled ---------------------
#define TILE 4096
__global__ void k_sort() {
    __shared__ unsigned long long sk[TILE];
    unsigned long long* keys = g_keys[blockIdx.x];

    // local phase: k = 2..TILE entirely within tiles
    for (int t = 0; t < NE / TILE; t++) {
        unsigned long long* base = keys + t * TILE;
        for (int i = threadIdx.x; i < TILE; i += blockDim.x) sk[i] = base[i];
        __syncthreads();
        for (int k = 2; k <= TILE; k <<= 1) {
            for (int j = k >> 1; j > 0; j >>= 1) {
                for (int p = threadIdx.x; p < TILE / 2; p += blockDim.x) {
                    int i = 2 * j * (p / j) + (p % j);
                    int ixj = i + j;
                    bool up = (((t * TILE + i) & k) == 0);
                    unsigned long long A = sk[i], B = sk[ixj];
                    if ((A > B) == up) { sk[i] = B; sk[ixj] = A; }
                }
                __syncthreads();
            }
        }
        for (int i = threadIdx.x; i < TILE; i += blockDim.x) base[i] = sk[i];
        __syncthreads();
    }

    // merge phases: global steps for j >= TILE, tiled steps for j < TILE
    for (int k = TILE << 1; k <= NE; k <<= 1) {
        for (int j = k >> 1; j >= TILE; j >>= 1) {
            for (int p = threadIdx.x; p < NE / 2; p += blockDim.x) {
                int i = 2 * j * (p / j) + (p % j);
                int ixj = i + j;
                bool up = ((i & k) == 0);
                unsigned long long A = keys[i], B = keys[ixj];
                if ((A > B) == up) { keys[i] = B; keys[ixj] = A; }
            }
            __syncthreads();
        }
        for (int t = 0; t < NE / TILE; t++) {
            unsigned long long* base = keys + t * TILE;
            for (int i = threadIdx.x; i < TILE; i += blockDim.x) sk[i] = base[i];
            __syncthreads();
            for (int j = TILE >> 1; j > 0; j >>= 1) {
                for (int p = threadIdx.x; p < TILE / 2; p += blockDim.x) {
                    int i = 2 * j * (p / j) + (p % j);
                    int ixj = i + j;
                    bool up = (((t * TILE + i) & k) == 0);
                    unsigned long long A = sk[i], B = sk[ixj];
                    if ((A > B) == up) { sk[i] = B; sk[ixj] = A; }
                }
                __syncthreads();
            }
            for (int i = threadIdx.x; i < TILE; i += blockDim.x) base[i] = sk[i];
            __syncthreads();
        }
    }
}

// ---------------- 4. decode sorted edges into streaming arrays -------------
__global__ void k_decode(const float* __restrict__ aff) {
    int i = blockIdx.x * blockDim.x + threadIdx.x;   // b*NE + rank
    if (i >= BATCH * NE) return;
    int b = i / NE;
    int r = i - b * NE;
    unsigned long long kk = g_keys[b][r];
    int e = (int)(kk & 0xffffffffu);
    int c = (e >= HW) ? 1 : 0;
    int p = e - c * HW;
    int row = p >> 7, col = p & (Ww - 1);
    int u = 0, v = 0;                    // invalid boundary edge -> self edge (skip)
    if (!c) { if (row < Hh - 1) { u = p; v = p + Ww; } }
    else    { if (col < Ww - 1) { u = p; v = p + 1;  } }
    g_u[b][r] = (unsigned short)u;
    g_v[b][r] = (unsigned short)v;
    g_a[b][r] = aff[b * NE + e];
}

// ---------------- 5. windowed parallel Kruskal + MALIS (1 warp/batch) ------
__global__ void k_scan(const int* __restrict__ gt) {
    extern __shared__ unsigned short sh[];
    unsigned short* par   = sh;             // union-find parent
    unsigned short* szs   = sh + HW;        // component size
    unsigned short* nzs   = sh + 2 * HW;    // nonzero-label voxel count
    unsigned*       claim = (unsigned*)(sh + 3 * HW);  // monotone claim tags
    int b = blockIdx.x;

    for (int i = threadIdx.x; i < HW; i += blockDim.x) {
        par[i] = (unsigned short)i;
        szs[i] = 1;
        nzs[i] = (gt[b * HW + i] != 0) ? 1 : 0;
        claim[i] = 0;
    }
    __syncthreads();
    if (threadIdx.x >= 32) return;        // warp 0 only from here on

    const int lane = threadIdx.x;
    const unsigned short* up_ = g_u[b];
    const unsigned short* vp_ = g_v[b];
    const float*          ap_ = g_a[b];

    // ======== PASS 1: claim-parallel Kruskal, Sum(tutv*a), merge records ===
    double gacc = 0.0;    // lane-local
    int M = 0;            // uniform merge count
    unsigned rc = 1;      // global round counter -> monotone tags

    for (int e0 = 0; e0 < NE; e0 += 32) {
        int e = e0 + lane;
        int uu = up_[e], vv = vp_[e];
        float a = ap_[e];
        bool pending = (uu != vv);

        while (__any_sync(FULLW, pending)) {
            int ru = 0, rv = 0;
            if (pending) {
                // parallel finds with path compression (concurrent compression
                // writes are benign: all write true roots)
                ru = uu; while (true) { int p = par[ru]; if (p == ru) break; ru = p; }
                { int x = uu; while (par[x] != ru) { int nx = par[x]; par[x] = (unsigned short)ru; x = nx; } }
                rv = vv; while (true) { int p = par[rv]; if (p == rv) break; rv = p; }
                { int x = vv; while (par[x] != rv) { int nx = par[x]; par[x] = (unsigned short)rv; x = nx; } }
                if (ru == rv) pending = false;   // non-merge: retire, no ordering needed
            }
            __syncwarp();
            unsigned tag = (rc << 6) | (unsigned)(63 - lane);  // earlier lane = larger tag
            if (pending) {
                atomicMax(&claim[ru], tag);
                atomicMax(&claim[rv], tag);
            }
            __syncwarp();
            bool win = pending && (claim[ru] == tag) && (claim[rv] == tag);
            unsigned wb = __ballot_sync(FULLW, win);
            if (win) {
                int su = szs[ru], sv = szs[rv];
                unsigned bigRv = (su < sv) ? 1u : 0u;
                int big   = bigRv ? rv : ru;
                int small = ru + rv - big;
                par[small] = (unsigned short)big;
                int tu = nzs[ru], tv = nzs[rv];
                szs[big] = (unsigned short)(su + sv);
                nzs[big] = (unsigned short)(tu + tv);
                gacc += (double)(tu * tv) * (double)a;
                int pos = M + __popc(wb & ((1u << lane) - 1u));
                g_rec[b][pos] = (unsigned)ru | ((unsigned)rv << 16) | (bigRv << 31);
                pending = false;
            }
            M += __popc(wb);
            rc++;
            __syncwarp();
        }
    }

    __threadfence_block();
    __syncwarp();

    // ======== PASS 2: histogram replay, Sum(same) (lane-private, MLP) ======
    long long acc = 0;
    unsigned short* cnt = &g_cnt[b][0][0];
    const unsigned* rec = g_rec[b];
    const int off = 2 * lane;

#pragma unroll 4
    for (int m = 0; m < M; m++) {
        unsigned r = rec[m];
        int ru = (int)(r & 0xffffu);
        int rv = (int)((r >> 16) & 0x7fffu);
        int big = (r >> 31) ? rv : ru;
        ushort2 cu = *reinterpret_cast<const ushort2*>(cnt + ru * NL + off);
        ushort2 cv = *reinterpret_cast<const ushort2*>(cnt + rv * NL + off);
        int prod = (int)cu.y * (int)cv.y + (lane ? (int)cu.x * (int)cv.x : 0); // skip label 0
        acc += prod;
        ushort2 cs;
        cs.x = (unsigned short)(cu.x + cv.x);
        cs.y = (unsigned short)(cu.y + cv.y);
        *reinterpret_cast<ushort2*>(cnt + big * NL + off) = cs;
    }

    // reduce Sum(same) and Sum(tutv*a) across lanes
#pragma unroll
    for (int s = 16; s; s >>= 1) {
        acc  += __shfl_xor_sync(FULLW, acc, s);
        gacc += __shfl_xor_sync(FULLW, gacc, s);
    }

    if (lane == 0)
        g_partial[b] = gacc - (double)acc;   // Sum over merges of (tutv*a - same)
}

// ---------------- 6. finalize scalar ---------------------------------------
__global__ void k_final(float* __restrict__ out) {
    out[0] = (float)(-0.5 * (g_partial[0] + g_partial[1]));
}

// ---------------------------------------------------------------------------
extern "C" void kernel_launch(void* const* d_in, const int* in_sizes, int n_in,
                              void* d_out, int out_size) {
    const float* aff = (const float*)d_in[0];      // [2,2,128,128] f32
    const int*   gt  = (const int*)d_in[1];        // [2,128,128] int32
    float* out = (float*)d_out;

    int shbytes = 3 * HW * (int)sizeof(unsigned short) + HW * (int)sizeof(unsigned);
    cudaFuncSetAttribute(k_scan, cudaFuncAttributeMaxDynamicSharedMemorySize, shbytes);

    k_init_counts<<<(BATCH * HW + 255) / 256, 256>>>(gt);
    k_build_keys <<<(BATCH * NE + 255) / 256, 256>>>(aff);
    k_sort       <<<BATCH, 1024>>>();
    k_decode     <<<(BATCH * NE + 255) / 256, 256>>>(aff);
    k_scan       <<<BATCH, 256, shbytes>>>(gt);
    k_final      <<<1, 1>>>(out);
}

// round 13
// speedup vs baseline: 10.4718x; 4.6583x over previous
#include <cuda_runtime.h>
#include <stdint.h>

#define BATCH 2
#define Hh 128
#define Ww 128
#define HW (Hh * Ww)          // 16384 nodes
#define NE (2 * HW)           // 32768 edges per batch
#define NL 64                 // labels
#define WIN 256               // edges per block window
#define FULLW 0xffffffffu

// ---------------- static device scratch (no allocation allowed) ------------
__device__ __align__(256) unsigned long long g_keys[BATCH][NE];    // sort keys
__device__ __align__(256) unsigned short     g_u[BATCH][NE];
__device__ __align__(256) unsigned short     g_v[BATCH][NE];
__device__ __align__(256) float              g_a[BATCH][NE];
__device__ double    g_partial[BATCH];   // Sum over merges of tu*tv*a
__device__ long long g_same[BATCH];      // Sum_l>=1 C(N_l,2)

// ---------------- 1. build sort keys (descending affinity) -----------------
__global__ void k_build_keys(const float* __restrict__ aff) {
    int i = blockIdx.x * blockDim.x + threadIdx.x;   // b*NE + e
    if (i >= BATCH * NE) return;
    int b = i / NE;
    int e = i - b * NE;
    unsigned bits = __float_as_uint(aff[i]) | 0x80000000u;
    unsigned key  = ~bits;   // descending affinity under ascending uint sort
    g_keys[b][e] = ((unsigned long long)key << 32) | (unsigned)e;
}

// ---------------- 2. bitonic sort, shared-memory tiled ---------------------
#define TILE 4096
__global__ void k_sort() {
    __shared__ unsigned long long sk[TILE];
    unsigned long long* keys = g_keys[blockIdx.x];

    // local phase: k = 2..TILE entirely within tiles
    for (int t = 0; t < NE / TILE; t++) {
        unsigned long long* base = keys + t * TILE;
        for (int i = threadIdx.x; i < TILE; i += blockDim.x) sk[i] = base[i];
        __syncthreads();
        for (int k = 2; k <= TILE; k <<= 1) {
            for (int j = k >> 1; j > 0; j >>= 1) {
                for (int p = threadIdx.x; p < TILE / 2; p += blockDim.x) {
                    int i = 2 * j * (p / j) + (p % j);
                    int ixj = i + j;
                    bool up = (((t * TILE + i) & k) == 0);
                    unsigned long long A = sk[i], B = sk[ixj];
                    if ((A > B) == up) { sk[i] = B; sk[ixj] = A; }
                }
                __syncthreads();
            }
        }
        for (int i = threadIdx.x; i < TILE; i += blockDim.x) base[i] = sk[i];
        __syncthreads();
    }

    // merge phases: global steps for j >= TILE, tiled steps for j < TILE
    for (int k = TILE << 1; k <= NE; k <<= 1) {
        for (int j = k >> 1; j >= TILE; j >>= 1) {
            for (int p = threadIdx.x; p < NE / 2; p += blockDim.x) {
                int i = 2 * j * (p / j) + (p % j);
                int ixj = i + j;
                bool up = ((i & k) == 0);
                unsigned long long A = keys[i], B = keys[ixj];
                if ((A > B) == up) { keys[i] = B; keys[ixj] = A; }
            }
            __syncthreads();
        }
        for (int t = 0; t < NE / TILE; t++) {
            unsigned long long* base = keys + t * TILE;
            for (int i = threadIdx.x; i < TILE; i += blockDim.x) sk[i] = base[i];
            __syncthreads();
            for (int j = TILE >> 1; j > 0; j >>= 1) {
                for (int p = threadIdx.x; p < TILE / 2; p += blockDim.x) {
                    int i = 2 * j * (p / j) + (p % j);
                    int ixj = i + j;
                    bool up = (((t * TILE + i) & k) == 0);
                    unsigned long long A = sk[i], B = sk[ixj];
                    if ((A > B) == up) { sk[i] = B; sk[ixj] = A; }
                }
                __syncthreads();
            }
            for (int i = threadIdx.x; i < TILE; i += blockDim.x) base[i] = sk[i];
            __syncthreads();
        }
    }
}

// ---------------- 3. decode sorted edges into streaming arrays -------------
__global__ void k_decode(const float* __restrict__ aff) {
    int i = blockIdx.x * blockDim.x + threadIdx.x;   // b*NE + rank
    if (i >= BATCH * NE) return;
    int b = i / NE;
    int r = i - b * NE;
    unsigned long long kk = g_keys[b][r];
    int e = (int)(kk & 0xffffffffu);
    int c = (e >= HW) ? 1 : 0;
    int p = e - c * HW;
    int row = p >> 7, col = p & (Ww - 1);
    int u = 0, v = 0;                    // invalid boundary edge -> self edge (skip)
    if (!c) { if (row < Hh - 1) { u = p; v = p + Ww; } }
    else    { if (col < Ww - 1) { u = p; v = p + 1;  } }
    g_u[b][r] = (unsigned short)u;
    g_v[b][r] = (unsigned short)v;
    g_a[b][r] = aff[b * NE + e];
}

// ---------------- 4. same-label pair total: Sum_l>=1 C(N_l,2) --------------
__global__ void k_hist(const int* __restrict__ gt) {
    __shared__ int h[NL];
    int b = blockIdx.x;
    if (threadIdx.x < NL) h[threadIdx.x] = 0;
    __syncthreads();
    for (int i = threadIdx.x; i < HW; i += blockDim.x)
        atomicAdd(&h[gt[b * HW + i]], 1);
    __syncthreads();
    if (threadIdx.x == 0) {
        long long s = 0;
        for (int l = 1; l < NL; l++) {
            long long n = h[l];
            s += n * (n - 1) / 2;
        }
        g_same[b] = s;
    }
}

// ---------------- 5. block-parallel claim Kruskal (1 block/batch) ----------
__global__ void k_scan(const int* __restrict__ gt) {
    extern __shared__ unsigned short sh[];
    unsigned short* par   = sh;             // union-find parent
    unsigned short* szs   = sh + HW;        // component size
    unsigned short* nzs   = sh + 2 * HW;    // nonzero-label voxel count
    unsigned*       claim = (unsigned*)(sh + 3 * HW);  // monotone claim tags
    __shared__ double sred[WIN];
    int b = blockIdx.x;
    int tid = threadIdx.x;

    for (int i = tid; i < HW; i += blockDim.x) {
        par[i] = (unsigned short)i;
        szs[i] = 1;
        nzs[i] = (gt[b * HW + i] != 0) ? 1 : 0;
        claim[i] = 0;
    }
    __syncthreads();

    const unsigned short* up_ = g_u[b];
    const unsigned short* vp_ = g_v[b];
    const float*          ap_ = g_a[b];

    double gacc = 0.0;    // thread-local Sum(tu*tv*a)
    unsigned rc = 1;      // monotone round counter

    for (int w0 = 0; w0 < NE; w0 += WIN) {
        int e = w0 + tid;
        int uu = up_[e], vv = vp_[e];
        float a = ap_[e];
        bool pending = (uu != vv);

        int np = __syncthreads_count(pending ? 1 : 0);
        while (np) {
            int ru = 0, rv = 0;
            if (pending) {
                // parallel finds with path compression (no merges during this
                // phase -> all concurrent compression writes store true roots)
                ru = uu; while (true) { int p = par[ru]; if (p == ru) break; ru = p; }
                { int x = uu; while (par[x] != ru) { int nx = par[x]; par[x] = (unsigned short)ru; x = nx; } }
                rv = vv; while (true) { int p = par[rv]; if (p == rv) break; rv = p; }
                { int x = vv; while (par[x] != rv) { int nx = par[x]; par[x] = (unsigned short)rv; x = nx; } }
                if (ru == rv) pending = false;   // non-merge: retire (safe: connectivity only grows)
            }
            __syncthreads();
            unsigned tag = (rc << 8) | (unsigned)(255 - tid);  // earlier edge = larger tag
            if (pending) {
                atomicMax(&claim[ru], tag);
                atomicMax(&claim[rv], tag);
            }
            __syncthreads();
            bool win = pending && (claim[ru] == tag) && (claim[rv] == tag);
            if (win) {
                // no earlier pending edge touches ru/rv -> sequential-state match
                int su = szs[ru], sv = szs[rv];
                int big   = (su >= sv) ? ru : rv;
                int small = ru + rv - big;
                par[small] = (unsigned short)big;
                int tu = nzs[ru], tv = nzs[rv];
                szs[big] = (unsigned short)(su + sv);
                nzs[big] = (unsigned short)(tu + tv);
                gacc += (double)(tu * tv) * (double)a;
                pending = false;
            }
            rc++;
            np = __syncthreads_count(pending ? 1 : 0);
        }
    }

    // block reduction of gacc
    sred[tid] = gacc;
    __syncthreads();
    for (int s = WIN / 2; s > 0; s >>= 1) {
        if (tid < s) sred[tid] += sred[tid + s];
        __syncthreads();
    }
    if (tid == 0) g_partial[b] = sred[0];
}

// ---------------- 6. finalize scalar ---------------------------------------
__global__ void k_final(float* __restrict__ out) {
    double t0 = g_partial[0] - (double)g_same[0];
    double t1 = g_partial[1] - (double)g_same[1];
    out[0] = (float)(-0.5 * (t0 + t1));
}

// ---------------------------------------------------------------------------
extern "C" void kernel_launch(void* const* d_in, const int* in_sizes, int n_in,
                              void* d_out, int out_size) {
    const float* aff = (const float*)d_in[0];      // [2,2,128,128] f32
    const int*   gt  = (const int*)d_in[1];        // [2,128,128] int32
    float* out = (float*)d_out;

    int shbytes = 3 * HW * (int)sizeof(unsigned short) + HW * (int)sizeof(unsigned);
    cudaFuncSetAttribute(k_scan, cudaFuncAttributeMaxDynamicSharedMemorySize, shbytes);

    k_build_keys<<<(BATCH * NE + 255) / 256, 256>>>(aff);
    k_sort      <<<BATCH, 1024>>>();
    k_decode    <<<(BATCH * NE + 255) / 256, 256>>>(aff);
    k_hist      <<<BATCH, 256>>>(gt);
    k_scan      <<<BATCH, WIN, shbytes>>>(gt);
    k_final     <<<1, 1>>>(out);
}

// round 14
// speedup vs baseline: 15.5842x; 1.4882x over previous
#include <cuda_runtime.h>
#include <stdint.h>

#define BATCH 2
#define Hh 128
#define Ww 128
#define HW (Hh * Ww)          // 16384 nodes
#define NE (2 * HW)           // 32768 edges per batch
#define NL 64                 // labels
#define WIN 512               // edges per block window (== k_scan blockDim)
#define TILE 4096             // sort tile (fits shared: 32 KB)
#define NTILES (NE / TILE)    // 8 tiles per batch

// ---------------- static device scratch (no allocation allowed) ------------
__device__ __align__(256) unsigned long long g_keys[BATCH][NE];    // sort keys
__device__ __align__(256) unsigned short     g_u[BATCH][NE];
__device__ __align__(256) unsigned short     g_v[BATCH][NE];
__device__ __align__(256) float              g_a[BATCH][NE];
__device__ double    g_partial[BATCH];   // Sum over merges of tu*tv*a
__device__ long long g_same[BATCH];      // Sum_l>=1 C(N_l,2)

// ---------------- 1. build sort keys (descending affinity) -----------------
__global__ void k_build_keys(const float* __restrict__ aff) {
    int i = blockIdx.x * blockDim.x + threadIdx.x;   // b*NE + e
    if (i >= BATCH * NE) return;
    int b = i / NE;
    int e = i - b * NE;
    unsigned bits = __float_as_uint(aff[i]) | 0x80000000u;
    unsigned key  = ~bits;   // descending affinity under ascending uint sort
    g_keys[b][e] = ((unsigned long long)key << 32) | (unsigned)e;
}

// ---------------- 2a. local bitonic sort of each 4096-tile -----------------
__global__ void k_sort_local() {
    __shared__ unsigned long long sk[TILE];
    int b = blockIdx.x / NTILES;
    int t = blockIdx.x % NTILES;
    unsigned long long* base = g_keys[b] + t * TILE;

    for (int i = threadIdx.x; i < TILE; i += blockDim.x) sk[i] = base[i];
    __syncthreads();
    for (int k = 2; k <= TILE; k <<= 1) {
        for (int j = k >> 1; j > 0; j >>= 1) {
            for (int p = threadIdx.x; p < TILE / 2; p += blockDim.x) {
                int i = 2 * j * (p / j) + (p % j);
                int ixj = i + j;
                bool up = (((t * TILE + i) & k) == 0);
                unsigned long long A = sk[i], B = sk[ixj];
                if ((A > B) == up) { sk[i] = B; sk[ixj] = A; }
            }
            __syncthreads();
        }
    }
    for (int i = threadIdx.x; i < TILE; i += blockDim.x) base[i] = sk[i];
}

// ---------------- 2b. one global compare-exchange step (j >= TILE) ---------
__global__ void k_sort_gstep(int k, int j) {
    int p = blockIdx.x * blockDim.x + threadIdx.x;   // [0, BATCH*NE/2)
    int b = p / (NE / 2);
    int q = p - b * (NE / 2);
    int i = 2 * j * (q / j) + (q % j);
    int ixj = i + j;
    unsigned long long* keys = g_keys[b];
    unsigned long long A = keys[i], B = keys[ixj];
    bool up = ((i & k) == 0);
    if ((A > B) == up) { keys[i] = B; keys[ixj] = A; }
}

// ---------------- 2c. tiled finish of a merge stage (j <= TILE/2) ----------
__global__ void k_sort_tiled(int k) {
    __shared__ unsigned long long sk[TILE];
    int b = blockIdx.x / NTILES;
    int t = blockIdx.x % NTILES;
    unsigned long long* base = g_keys[b] + t * TILE;

    for (int i = threadIdx.x; i < TILE; i += blockDim.x) sk[i] = base[i];
    __syncthreads();
    for (int j = TILE >> 1; j > 0; j >>= 1) {
        for (int p = threadIdx.x; p < TILE / 2; p += blockDim.x) {
            int i = 2 * j * (p / j) + (p % j);
            int ixj = i + j;
            bool up = (((t * TILE + i) & k) == 0);
            unsigned long long A = sk[i], B = sk[ixj];
            if ((A > B) == up) { sk[i] = B; sk[ixj] = A; }
        }
        __syncthreads();
    }
    for (int i = threadIdx.x; i < TILE; i += blockDim.x) base[i] = sk[i];
}

// ---------------- 3. decode sorted edges into streaming arrays -------------
__global__ void k_decode(const float* __restrict__ aff) {
    int i = blockIdx.x * blockDim.x + threadIdx.x;   // b*NE + rank
    if (i >= BATCH * NE) return;
    int b = i / NE;
    int r = i - b * NE;
    unsigned long long kk = g_keys[b][r];
    int e = (int)(kk & 0xffffffffu);
    int c = (e >= HW) ? 1 : 0;
    int p = e - c * HW;
    int row = p >> 7, col = p & (Ww - 1);
    int u = 0, v = 0;                    // invalid boundary edge -> self edge (skip)
    if (!c) { if (row < Hh - 1) { u = p; v = p + Ww; } }
    else    { if (col < Ww - 1) { u = p; v = p + 1;  } }
    g_u[b][r] = (unsigned short)u;
    g_v[b][r] = (unsigned short)v;
    g_a[b][r] = aff[b * NE + e];
}

// ---------------- 4. same-label pair total: Sum_l>=1 C(N_l,2) --------------
__global__ void k_hist(const int* __restrict__ gt) {
    __shared__ int h[16][NL];     // per-warp sub-histograms
    int b = blockIdx.x;
    int w = threadIdx.x >> 5;
    int nw = blockDim.x >> 5;
    for (int i = threadIdx.x; i < 16 * NL; i += blockDim.x)
        ((int*)h)[i] = 0;
    __syncthreads();
    for (int i = threadIdx.x; i < HW; i += blockDim.x)
        atomicAdd(&h[w][gt[b * HW + i]], 1);
    __syncthreads();
    if (threadIdx.x < NL) {
        int l = threadIdx.x;
        int n = 0;
        for (int ww = 0; ww < nw; ww++) n += h[ww][l];
        h[0][l] = (l == 0) ? 0 : n;
    }
    __syncthreads();
    if (threadIdx.x == 0) {
        long long s = 0;
        for (int l = 1; l < NL; l++) {
            long long n = h[0][l];
            s += n * (n - 1) / 2;
        }
        g_same[b] = s;
    }
}

// ---------------- 5. block-parallel claim Kruskal (1 block/batch) ----------
__global__ void k_scan(const int* __restrict__ gt) {
    extern __shared__ unsigned short sh[];
    unsigned short* par   = sh;             // union-find parent
    unsigned short* szs   = sh + HW;        // component size
    unsigned short* nzs   = sh + 2 * HW;    // nonzero-label voxel count
    unsigned*       claim = (unsigned*)(sh + 3 * HW);  // monotone claim tags
    __shared__ double sred[WIN];
    int b = blockIdx.x;
    int tid = threadIdx.x;

    for (int i = tid; i < HW; i += blockDim.x) {
        par[i] = (unsigned short)i;
        szs[i] = 1;
        nzs[i] = (gt[b * HW + i] != 0) ? 1 : 0;
        claim[i] = 0;
    }
    __syncthreads();

    const unsigned short* up_ = g_u[b];
    const unsigned short* vp_ = g_v[b];
    const float*          ap_ = g_a[b];

    double gacc = 0.0;    // thread-local Sum(tu*tv*a)
    unsigned rc = 1;      // monotone round counter

    for (int w0 = 0; w0 < NE; w0 += WIN) {
        int e = w0 + tid;
        int uu = up_[e], vv = vp_[e];
        float a = ap_[e];
        bool pending = (uu != vv);

        int np = __syncthreads_count(pending ? 1 : 0);
        while (np) {
            int ru = 0, rv = 0;
            unsigned tag = (rc << 10) | (unsigned)(1023 - tid);  // earlier edge = larger tag
            if (pending) {
                // parallel finds with path compression (no merges in-flight ->
                // all concurrent compression writes store true roots), then
                // immediately claim both roots (claim[] disjoint from par[])
                ru = uu; while (true) { int p = par[ru]; if (p == ru) break; ru = p; }
                { int x = uu; while (par[x] != ru) { int nx = par[x]; par[x] = (unsigned short)ru; x = nx; } }
                rv = vv; while (true) { int p = par[rv]; if (p == rv) break; rv = p; }
                { int x = vv; while (par[x] != rv) { int nx = par[x]; par[x] = (unsigned short)rv; x = nx; } }
                if (ru == rv) pending = false;   // non-merge: retire (connectivity only grows)
                else { atomicMax(&claim[ru], tag); atomicMax(&claim[rv], tag); }
            }
            __syncthreads();
            bool win = pending && (claim[ru] == tag) && (claim[rv] == tag);
            if (win) {
                // no earlier pending edge touches ru/rv -> sequential-state match
                int su = szs[ru], sv = szs[rv];
                int big   = (su >= sv) ? ru : rv;
                int small = ru + rv - big;
                par[small] = (unsigned short)big;
                int tu = nzs[ru], tv = nzs[rv];
                szs[big] = (unsigned short)(su + sv);
                nzs[big] = (unsigned short)(tu + tv);
                gacc += (double)(tu * tv) * (double)a;
                pending = false;
            }
            rc++;
            np = __syncthreads_count(pending ? 1 : 0);
        }
    }

    // block reduction of gacc
    sred[tid] = gacc;
    __syncthreads();
    for (int s = WIN / 2; s > 0; s >>= 1) {
        if (tid < s) sred[tid] += sred[tid + s];
        __syncthreads();
    }
    if (tid == 0) g_partial[b] = sred[0];
}

// ---------------- 6. finalize scalar ---------------------------------------
__global__ void k_final(float* __restrict__ out) {
    double t0 = g_partial[0] - (double)g_same[0];
    double t1 = g_partial[1] - (double)g_same[1];
    out[0] = (float)(-0.5 * (t0 + t1));
}

// ---------------------------------------------------------------------------
extern "C" void kernel_launch(void* const* d_in, const int* in_sizes, int n_in,
                              void* d_out, int out_size) {
    const float* aff = (const float*)d_in[0];      // [2,2,128,128] f32
    const int*   gt  = (const int*)d_in[1];        // [2,128,128] int32
    float* out = (float*)d_out;

    int shbytes = 3 * HW * (int)sizeof(unsigned short) + HW * (int)sizeof(unsigned);
    cudaFuncSetAttribute(k_scan, cudaFuncAttributeMaxDynamicSharedMemorySize, shbytes);

    k_build_keys<<<(BATCH * NE + 255) / 256, 256>>>(aff);

    // multi-block bitonic sort
    k_sort_local<<<BATCH * NTILES, 512>>>();
    int gblocks = (BATCH * NE / 2) / 256;
    for (int k = TILE << 1; k <= NE; k <<= 1) {
        for (int j = k >> 1; j >= TILE; j >>= 1)
            k_sort_gstep<<<gblocks, 256>>>(k, j);
        k_sort_tiled<<<BATCH * NTILES, 512>>>(k);
    }

    k_decode<<<(BATCH * NE + 255) / 256, 256>>>(aff);
    k_hist  <<<BATCH, 512>>>(gt);
    k_scan  <<<BATCH, WIN, shbytes>>>(gt);
    k_final <<<1, 1>>>(out);
}